// round 16
// baseline (speedup 1.0000x reference)
#include <cuda_runtime.h>
#include <cuda_fp16.h>
#include <math.h>
#include <stdint.h>

#define N_NODES 8192
#define D 256
#define NG 8
#define ELLW 768   // max row degree bound; binomial(8192,0.05) max ~ 490

// ---------------- device scratch (no allocations allowed) ----------------
__device__ unsigned short g_cols[(size_t)N_NODES * ELLW];
__device__ float          g_coeff[(size_t)N_NODES * ELLW];
__device__ int            g_jtstart[(size_t)N_NODES * 65];   // CSR offsets per 128-col window
__device__ int            g_deg[N_NODES];
__device__ float          g_X1[(size_t)N_NODES * D];
__device__ float          g_X2[(size_t)N_NODES * D];
__device__ __half2        g_Xh[(size_t)N_NODES * (D / 2)];   // fp16 copy of layer input
__device__ __half2        g_Wh[(size_t)D * (D / 2)];         // fp16 copy of W
__device__ __half2        g_h2[(size_t)N_NODES * (D / 2)];   // h = X @ W, fp16 row-major
__device__ float          g_s1[N_NODES];
__device__ float          g_s2[N_NODES];
__device__ float          g_q[N_NODES];
__device__ float          g_invZ[N_NODES];
__device__ float          g_wa[D];
__device__ float          g_wb[D];
__device__ float          g_Spart[32][D];
__device__ float          g_S[D];
__device__ float          g_mid[(size_t)N_NODES * 64];
__device__ float          g_gpart[(size_t)64 * NG * D];
__device__ int            g_gcntp[64 * NG];
__device__ float          g_gsum[NG * D];
__device__ float          g_gcnt[NG];

// ---------------- helpers ----------------
__device__ __forceinline__ float gelu_exact(float x) {
    return 0.5f * x * (1.0f + erff(x * 0.70710678118654752f));
}

__device__ __forceinline__ uint32_t smem_addr(const void* p) {
    return (uint32_t)__cvta_generic_to_shared(p);
}

__device__ __forceinline__ void cp_async16(uint32_t dst, const void* src) {
    asm volatile("cp.async.cg.shared.global [%0], [%1], 16;" :: "r"(dst), "l"(src));
}
__device__ __forceinline__ void cp_commit() {
    asm volatile("cp.async.commit_group;");
}
__device__ __forceinline__ void cp_wait1() {
    asm volatile("cp.async.wait_group 1;");
}
__device__ __forceinline__ void cp_wait0() {
    asm volatile("cp.async.wait_group 0;");
}

__device__ __forceinline__ void ldsm_x4(uint32_t addr, uint32_t& r0, uint32_t& r1,
                                        uint32_t& r2, uint32_t& r3) {
    asm volatile("ldmatrix.sync.aligned.m8n8.x4.shared.b16 {%0,%1,%2,%3}, [%4];"
                 : "=r"(r0), "=r"(r1), "=r"(r2), "=r"(r3) : "r"(addr));
}

__device__ __forceinline__ void ldsm_x2_trans(uint32_t addr, uint32_t& r0, uint32_t& r1) {
    asm volatile("ldmatrix.sync.aligned.m8n8.x2.trans.shared.b16 {%0,%1}, [%2];"
                 : "=r"(r0), "=r"(r1) : "r"(addr));
}

__device__ __forceinline__ void mma16816(float* c, uint32_t a0, uint32_t a1, uint32_t a2,
                                         uint32_t a3, uint32_t b0, uint32_t b1) {
    asm volatile(
        "mma.sync.aligned.m16n8k16.row.col.f32.f16.f16.f32 "
        "{%0,%1,%2,%3}, {%4,%5,%6,%7}, {%8,%9}, {%0,%1,%2,%3};"
        : "+f"(c[0]), "+f"(c[1]), "+f"(c[2]), "+f"(c[3])
        : "r"(a0), "r"(a1), "r"(a2), "r"(a3), "r"(b0), "r"(b1));
}

// ---------------- 0: dense adj -> ELL (deterministic, sorted cols) ----------------
__global__ void build_ell_kernel(const float* __restrict__ adj) {
    int i = blockIdx.x;
    int tid = threadIdx.x;             // 256
    int lane = tid & 31, w = tid >> 5;
    __shared__ int wcnt[8];
    const float* row = adj + (size_t)i * N_NODES;
    int base = 0;
    for (int c0 = 0; c0 < N_NODES; c0 += 256) {
        int c = c0 + tid;
        bool pred = (row[c] != 0.0f);
        unsigned bal = __ballot_sync(0xffffffffu, pred);
        if (lane == 0) wcnt[w] = __popc(bal);
        __syncthreads();
        int off = 0, tot = 0;
#pragma unroll
        for (int k = 0; k < 8; k++) { int v = wcnt[k]; tot += v; if (k < w) off += v; }
        if (pred) {
            int pos = base + off + __popc(bal & ((1u << lane) - 1u));
            if (pos < ELLW) g_cols[(size_t)i * ELLW + pos] = (unsigned short)c;
        }
        base += tot;
        __syncthreads();
    }
    if (tid == 0) g_deg[i] = (base < ELLW) ? base : ELLW;
}

// ---------------- 1: wa = W @ a_top, wb = W @ a_bot ----------------
__global__ void wavec_kernel(const float* __restrict__ W, const float* __restrict__ a) {
    __shared__ float at[D], ab[D];
    int t = threadIdx.x; // 256
    at[t] = a[t];
    ab[t] = a[D + t];
    __syncthreads();
    float s1 = 0.0f, s2 = 0.0f;
    const float* wr = W + (size_t)t * D;
#pragma unroll 8
    for (int c = 0; c < D; c++) { float w = wr[c]; s1 += w * at[c]; s2 += w * ab[c]; }
    g_wa[t] = s1;
    g_wb[t] = s2;
}

// ---------------- 2: s1 = X @ wa, s2 = X @ wb (fp32 exact logit path) ----------------
__global__ void s12_kernel(const float* __restrict__ X) {
    int w = threadIdx.x >> 5, lane = threadIdx.x & 31;
    int i = blockIdx.x * 8 + w;
    const float* xr = X + (size_t)i * D;
    float a1 = 0.0f, a2 = 0.0f;
#pragma unroll
    for (int jj = 0; jj < 8; jj++) {
        int j = jj * 32 + lane;
        float x = xr[j];
        a1 += x * g_wa[j];
        a2 += x * g_wb[j];
    }
#pragma unroll
    for (int o = 16; o > 0; o >>= 1) {
        a1 += __shfl_down_sync(0xffffffffu, a1, o);
        a2 += __shfl_down_sync(0xffffffffu, a2, o);
    }
    if (lane == 0) { g_s1[i] = a1; g_s2[i] = a2; }
}

// ---------------- 2b: fp32 -> fp16 conversion (4 floats per thread) ----------------
__global__ void cvt_half_kernel(const float* __restrict__ A, __half2* __restrict__ O) {
    int idx = blockIdx.x * blockDim.x + threadIdx.x;
    float4 v = reinterpret_cast<const float4*>(A)[idx];
    O[idx * 2]     = __floats2half2_rn(v.x, v.y);
    O[idx * 2 + 1] = __floats2half2_rn(v.z, v.w);
}

// ---------------- 3a: fp16 tensor GEMM  g_h2 = Ah(8192x256) @ Bh(256x256) ----------------
__global__ __launch_bounds__(256) void h16_gemm_kernel(const __half* __restrict__ Ah,
                                                       const __half* __restrict__ Bh) {
    __shared__ __align__(16) __half As[128 * 72];   // row stride 144 B (conflict-free ldsm)
    __shared__ __align__(16) __half Bs[64 * 72];
    const int tid = threadIdx.x, lane = tid & 31, wid = tid >> 5;
    const int wm = wid >> 1, wn = wid & 1;
    const int m0 = blockIdx.y * 128, n0 = blockIdx.x * 64;
    float acc[2][4][4];
#pragma unroll
    for (int m = 0; m < 2; m++)
#pragma unroll
        for (int n = 0; n < 4; n++)
#pragma unroll
            for (int j = 0; j < 4; j++) acc[m][n][j] = 0.0f;

    const uint32_t as_base = smem_addr(As);
    const uint32_t bs_base = smem_addr(Bs);
    const int ar = tid >> 1, aq = (tid & 1) * 4;
    const int br = tid >> 2, bq = (tid & 3) * 2;

    for (int kt = 0; kt < 4; kt++) {
        int k0 = kt * 64;
        {
            const uint4* asrc = reinterpret_cast<const uint4*>(Ah + (size_t)(m0 + ar) * 256 + k0);
            uint4* adst = reinterpret_cast<uint4*>(As + ar * 72);
#pragma unroll
            for (int c = 0; c < 4; c++) adst[aq + c] = asrc[aq + c];
        }
        {
            const uint4* bsrc = reinterpret_cast<const uint4*>(Bh + (size_t)(k0 + br) * 256 + n0);
            uint4* bdst = reinterpret_cast<uint4*>(Bs + br * 72);
            bdst[bq] = bsrc[bq];
            bdst[bq + 1] = bsrc[bq + 1];
        }
        __syncthreads();
#pragma unroll
        for (int k8 = 0; k8 < 4; k8++) {
            uint32_t a0[2], a1[2], a2[2], a3[2];
#pragma unroll
            for (int m = 0; m < 2; m++) {
                uint32_t addr = as_base +
                    (uint32_t)((wm * 32 + m * 16 + (lane & 15)) * 144 + (lane >> 4) * 16 + k8 * 32);
                ldsm_x4(addr, a0[m], a1[m], a2[m], a3[m]);
            }
#pragma unroll
            for (int n8 = 0; n8 < 4; n8++) {
                uint32_t baddr = bs_base +
                    (uint32_t)((k8 * 16 + (lane & 15)) * 144 + (wn * 32 + n8 * 8) * 2);
                uint32_t b0, b1;
                ldsm_x2_trans(baddr, b0, b1);
                mma16816(acc[0][n8], a0[0], a1[0], a2[0], a3[0], b0, b1);
                mma16816(acc[1][n8], a0[1], a1[1], a2[1], a3[1], b0, b1);
            }
        }
        __syncthreads();
    }
#pragma unroll
    for (int m = 0; m < 2; m++) {
        int r = m0 + wm * 32 + m * 16 + (lane >> 2);
#pragma unroll
        for (int n8 = 0; n8 < 4; n8++) {
            int cidx = n0 + wn * 32 + n8 * 8 + (lane & 3) * 2;
            g_h2[(size_t)r * 128 + (cidx >> 1)] = __floats2half2_rn(acc[m][n8][0], acc[m][n8][1]);
            g_h2[(size_t)(r + 8) * 128 + (cidx >> 1)] = __floats2half2_rn(acc[m][n8][2], acc[m][n8][3]);
        }
    }
}

// ---------------- 3b: fp32 GEMM (node head). BM=128,BN=64, 8x4 microtile ----------------
template <int ACT, int OUTH>
__global__ __launch_bounds__(256) void gemm_kernel(const float* __restrict__ A,
                                                   const float* __restrict__ B,
                                                   const float* __restrict__ bias,
                                                   void* __restrict__ C,
                                                   int M, int N, int K) {
    const int BM = 128, BN = 64, BK = 16;
    __shared__ __align__(16) float As[BK][BM];
    __shared__ __align__(16) float Bs[BK][BN];
    int tid = threadIdx.x;  // 256
    int m0 = blockIdx.y * BM, n0 = blockIdx.x * BN;
    int tx = tid & 15, ty = tid >> 4;
    float acc[8][4];
#pragma unroll
    for (int i = 0; i < 8; i++)
#pragma unroll
        for (int j = 0; j < 4; j++) acc[i][j] = 0.0f;

    int ar = tid >> 1;
    int ac = (tid & 1) * 8;
    int br = tid >> 4;
    int bc = (tid & 15) * 4;

    for (int k0 = 0; k0 < K; k0 += BK) {
        {
            const float* ap = &A[(size_t)(m0 + ar) * K + k0 + ac];
            float4 v0 = *reinterpret_cast<const float4*>(ap);
            float4 v1 = *reinterpret_cast<const float4*>(ap + 4);
            As[ac + 0][ar] = v0.x; As[ac + 1][ar] = v0.y;
            As[ac + 2][ar] = v0.z; As[ac + 3][ar] = v0.w;
            As[ac + 4][ar] = v1.x; As[ac + 5][ar] = v1.y;
            As[ac + 6][ar] = v1.z; As[ac + 7][ar] = v1.w;
        }
        {
            float4 v = *reinterpret_cast<const float4*>(&B[(size_t)(k0 + br) * N + n0 + bc]);
            *reinterpret_cast<float4*>(&Bs[br][bc]) = v;
        }
        __syncthreads();
#pragma unroll
        for (int kk = 0; kk < BK; kk++) {
            float4 a0 = *reinterpret_cast<const float4*>(&As[kk][ty * 8]);
            float4 a1 = *reinterpret_cast<const float4*>(&As[kk][ty * 8 + 4]);
            float4 bv = *reinterpret_cast<const float4*>(&Bs[kk][tx * 4]);
            float a8[8] = {a0.x, a0.y, a0.z, a0.w, a1.x, a1.y, a1.z, a1.w};
            float b4[4] = {bv.x, bv.y, bv.z, bv.w};
#pragma unroll
            for (int i = 0; i < 8; i++)
#pragma unroll
                for (int j = 0; j < 4; j++) acc[i][j] += a8[i] * b4[j];
        }
        __syncthreads();
    }
#pragma unroll
    for (int i = 0; i < 8; i++)
#pragma unroll
        for (int j = 0; j < 4; j++) {
            int r = m0 + ty * 8 + i, c = n0 + tx * 4 + j;
            float v = acc[i][j];
            if (ACT == 1) { v += bias[c]; v = gelu_exact(v); }
            if (OUTH) ((__half*)C)[(size_t)r * N + c] = __float2half(v);
            else      ((float*)C)[(size_t)r * N + c] = v;
        }
}

// ---------------- 4: column sum of h ----------------
__global__ void colsum_part_kernel() {
    int d = threadIdx.x, b = blockIdx.x;  // 32 blocks
    const __half* h = reinterpret_cast<const __half*>(g_h2);
    float s = 0.0f;
    int r0 = b * (N_NODES / 32);
    for (int r = r0; r < r0 + (N_NODES / 32); r++) s += __half2float(h[(size_t)r * D + d]);
    g_Spart[b][d] = s;
}
__global__ void colsum_red_kernel() {
    int d = threadIdx.x;
    float s = 0.0f;
#pragma unroll
    for (int b = 0; b < 32; b++) s += g_Spart[b][d];
    g_S[d] = s;
}

// ---------------- 5a: softmax constants + fp32 coefs + per-window CSR offsets ----------------
__global__ __launch_bounds__(256) void coef_kernel() {
    int wid = threadIdx.x >> 5, lane = threadIdx.x & 31;
    int i = blockIdx.x * 8 + wid;
    int deg = g_deg[i];
    float s1 = g_s1[i];
    const unsigned short* __restrict__ crow = g_cols + (size_t)i * ELLW;
    float* __restrict__ cfrow = g_coeff + (size_t)i * ELLW;
    int* __restrict__ jts = g_jtstart + (size_t)i * 65;

    float tmax = -1e30f;
    for (int k = lane; k < deg; k += 32) tmax = fmaxf(tmax, g_s2[crow[k]]);
#pragma unroll
    for (int o = 16; o > 0; o >>= 1) tmax = fmaxf(tmax, __shfl_xor_sync(0xffffffffu, tmax, o));

    float m;
    {
        float z = s1 + tmax;
        float lr = (z > 0.0f) ? z : 0.2f * z;
        m = fmaxf(lr, 0.0f);
        if (deg == 0) m = 0.0f;
    }
    float q = __expf(-m);

    float zs = 0.0f;
    for (int k = lane; k < deg; k += 32) {
        int c = (int)crow[k];
        float z = s1 + g_s2[c];
        float lr = (z > 0.0f) ? z : 0.2f * z;
        float p = __expf(lr - m);
        zs += p;
        cfrow[k] = p - q;
        int jtc = c >> 7;
        int prev = (k == 0) ? -1 : ((int)crow[k - 1] >> 7);
        for (int t = prev + 1; t <= jtc; t++) jts[t] = k;
        if (k == deg - 1)
            for (int t = jtc + 1; t <= 64; t++) jts[t] = deg;
    }
    if (deg == 0 && lane == 0)
        for (int t = 0; t <= 64; t++) jts[t] = 0;
#pragma unroll
    for (int o = 16; o > 0; o >>= 1) zs += __shfl_xor_sync(0xffffffffu, zs, o);

    if (lane == 0) {
        float Z = zs + (float)(N_NODES - deg) * q;
        g_q[i] = q;
        g_invZ[i] = 1.0f / Z;
    }
}

// ---------------- 5b: smem-windowed gather, warp-owned rows, counted loops ----------------
// 128 blocks x 64 rows, 512 threads = 16 warps. Warp w owns rows {w,w+16,w+32,w+48}:
// ALL edge instructions are warp-uniform (no masked divergence). Per 128-col window the
// h rows are staged into smem via double-buffered cp.async (R12-proven). Row bounds come
// from g_jtstart, loaded up-front per window (independent LDGs), giving counted inner
// loops the compiler can unroll for LDS MLP. Lane owns features [8*lane, 8*lane+8).
#define GT3_BUF_U4 4096                 // 128 rows x 32 uint4 = 64 KB per buffer
#define GT3_SMEM_BYTES (2 * 65536)

__global__ __launch_bounds__(512) void gat_tile3_kernel(const float* __restrict__ Xin,
                                                        const float* __restrict__ lng,
                                                        const float* __restrict__ lnb,
                                                        float* __restrict__ Xout,
                                                        __half2* __restrict__ XoutH,
                                                        int residual) {
    extern __shared__ __align__(16) uint4 smem4[];   // [2][GT3_BUF_U4]
    const int tid = threadIdx.x, lane = tid & 31, w = tid >> 5;   // 16 warps
    const int rowbase = blockIdx.x * 64;

    int gi4[4];
    const unsigned short* crow4[4];
    const float* cfrow4[4];
    const int* jts4[4];
    int cur4[4];
#pragma unroll
    for (int r = 0; r < 4; r++) {
        int gi = rowbase + w + 16 * r;
        gi4[r] = gi;
        crow4[r] = g_cols + (size_t)gi * ELLW;
        cfrow4[r] = g_coeff + (size_t)gi * ELLW;
        jts4[r] = g_jtstart + (size_t)gi * 65;
        cur4[r] = 0;
    }

    float acc[4][8];
#pragma unroll
    for (int r = 0; r < 4; r++)
#pragma unroll
        for (int f = 0; f < 8; f++) acc[r][f] = 0.0f;

    // cp.async staging: thread loads row bj (0..127), bytes [bq*128, bq*128+128)
    const int bj = tid >> 2, bq = tid & 3;
    const uint4* __restrict__ hsrc = reinterpret_cast<const uint4*>(g_h2);  // 32 uint4/row
    const uint32_t smem_base = smem_addr(smem4);

    auto loadB = [&](int buf, int jt) {
        uint32_t dst = smem_base + (uint32_t)((buf * GT3_BUF_U4 + bj * 32 + bq * 8) * 16);
        const uint4* src = hsrc + (size_t)(jt * 128 + bj) * 32 + bq * 8;
#pragma unroll
        for (int c = 0; c < 8; c++) cp_async16(dst + c * 16, src + c);
    };

    loadB(0, 0);
    cp_commit();

    for (int jt = 0; jt < 64; jt++) {
        const int buf = jt & 1;
        __syncthreads();   // all warps done reading buf^1
        if (jt < 63) {
            loadB(buf ^ 1, jt + 1);
            cp_commit();
            cp_wait1();    // window jt data complete
        } else {
            cp_wait0();
        }
        __syncthreads();   // window jt visible block-wide

        const uint4* bw = smem4 + buf * GT3_BUF_U4;
        // load all 4 row bounds first (independent LDGs -> overlapped latency)
        int hi[4];
#pragma unroll
        for (int r = 0; r < 4; r++) hi[r] = __ldg(&jts4[r][jt + 1]);
#pragma unroll
        for (int r = 0; r < 4; r++) {
            const unsigned short* crow = crow4[r];
            const float* cfrow = cfrow4[r];
            const int cbase = jt << 7;
            int k = cur4[r];
            const int ke = hi[r];
            cur4[r] = ke;
#pragma unroll 2
            for (; k < ke; k++) {
                int j = (int)crow[k] - cbase;      // warp-uniform
                float c = cfrow[k];                // warp-uniform
                uint4 v = bw[j * 32 + lane];       // 512B contiguous per warp: conflict-free
                const __half2* hv = reinterpret_cast<const __half2*>(&v);
                float2 f0 = __half22float2(hv[0]);
                float2 f1 = __half22float2(hv[1]);
                float2 f2 = __half22float2(hv[2]);
                float2 f3 = __half22float2(hv[3]);
                acc[r][0] += c * f0.x; acc[r][1] += c * f0.y;
                acc[r][2] += c * f1.x; acc[r][3] += c * f1.y;
                acc[r][4] += c * f2.x; acc[r][5] += c * f2.y;
                acc[r][6] += c * f3.x; acc[r][7] += c * f3.y;
            }
        }
    }

    // warp-local epilogue per row (validated in R15): +q*S, /Z, ELU, LN, residual,
    // fp32 out + fp16 out (next layer's h16_gemm input)
#pragma unroll
    for (int r = 0; r < 4; r++) {
        const int gi = gi4[r];
        const float q = g_q[gi];
        const float invZ = g_invZ[gi];
        const int f0i = 8 * lane;
        float4 S0 = *reinterpret_cast<const float4*>(&g_S[f0i]);
        float4 S1 = *reinterpret_cast<const float4*>(&g_S[f0i + 4]);
        float Sv[8] = {S0.x, S0.y, S0.z, S0.w, S1.x, S1.y, S1.z, S1.w};
        float vals[8];
        float sum = 0.0f;
#pragma unroll
        for (int f = 0; f < 8; f++) {
            float v = (acc[r][f] + q * Sv[f]) * invZ;
            v = (v > 0.0f) ? v : expm1f(v);
            vals[f] = v;
            sum += v;
        }
#pragma unroll
        for (int o = 16; o > 0; o >>= 1) sum += __shfl_xor_sync(0xffffffffu, sum, o);
        float mean = sum * (1.0f / 256.0f);
        float sq = 0.0f;
#pragma unroll
        for (int f = 0; f < 8; f++) { float d = vals[f] - mean; sq += d * d; }
#pragma unroll
        for (int o = 16; o > 0; o >>= 1) sq += __shfl_xor_sync(0xffffffffu, sq, o);
        float rstd = rsqrtf(sq * (1.0f / 256.0f) + 1e-5f);

        float4 g0 = *reinterpret_cast<const float4*>(&lng[f0i]);
        float4 g1 = *reinterpret_cast<const float4*>(&lng[f0i + 4]);
        float4 b0 = *reinterpret_cast<const float4*>(&lnb[f0i]);
        float4 b1 = *reinterpret_cast<const float4*>(&lnb[f0i + 4]);
        float gv[8] = {g0.x, g0.y, g0.z, g0.w, g1.x, g1.y, g1.z, g1.w};
        float bv[8] = {b0.x, b0.y, b0.z, b0.w, b1.x, b1.y, b1.z, b1.w};
        float y[8];
#pragma unroll
        for (int f = 0; f < 8; f++) y[f] = (vals[f] - mean) * rstd * gv[f] + bv[f];
        if (residual) {
            float4 x0 = *reinterpret_cast<const float4*>(&Xin[(size_t)gi * D + f0i]);
            float4 x1 = *reinterpret_cast<const float4*>(&Xin[(size_t)gi * D + f0i + 4]);
            y[0] += x0.x; y[1] += x0.y; y[2] += x0.z; y[3] += x0.w;
            y[4] += x1.x; y[5] += x1.y; y[6] += x1.z; y[7] += x1.w;
        }
        float4* od = reinterpret_cast<float4*>(Xout + (size_t)gi * D + f0i);
        od[0] = make_float4(y[0], y[1], y[2], y[3]);
        od[1] = make_float4(y[4], y[5], y[6], y[7]);
        __half2 h4[4];
#pragma unroll
        for (int e = 0; e < 4; e++) h4[e] = __floats2half2_rn(y[2 * e], y[2 * e + 1]);
        *reinterpret_cast<uint4*>(XoutH + (size_t)gi * 128 + lane * 4) =
            *reinterpret_cast<const uint4*>(h4);
    }
}

// ---------------- 6: node logits (8192x64)@(64x5)+b ----------------
__global__ void node_logits_kernel(const float* __restrict__ mid, const float* __restrict__ w2,
                                   const float* __restrict__ b2, float* __restrict__ out) {
    int i = blockIdx.x, t = threadIdx.x;  // 64
    __shared__ float sm[64];
    sm[t] = mid[(size_t)i * 64 + t];
    __syncthreads();
    if (t < 5) {
        float s = b2[t];
#pragma unroll 8
        for (int k = 0; k < 64; k++) s += sm[k] * w2[k * 5 + t];
        out[(size_t)i * 5 + t] = s;
    }
}

// ---------------- 7: deterministic segment pooling ----------------
__global__ void pool_part_kernel(const float* __restrict__ h3, const int* __restrict__ mask) {
    __shared__ float sacc[NG * D];
    int d = threadIdx.x;  // 256
    int b = blockIdx.x;   // 64 blocks x 128 rows
#pragma unroll
    for (int g = 0; g < NG; g++) sacc[g * D + d] = 0.0f;
    __syncthreads();
    int r0 = b * 128, lc = 0;
    for (int r = r0; r < r0 + 128; r++) {
        int g = mask[r];
        sacc[g * D + d] += h3[(size_t)r * D + d];
        if (d < NG && g == d) lc++;
    }
    __syncthreads();
#pragma unroll
    for (int g = 0; g < NG; g++)
        g_gpart[((size_t)b * NG + g) * D + d] = sacc[g * D + d];
    if (d < NG) g_gcntp[b * NG + d] = lc;
}
__global__ void pool_red_kernel() {
    int g = blockIdx.x, d = threadIdx.x;  // 8 x 256
    float s = 0.0f;
    for (int b = 0; b < 64; b++) s += g_gpart[((size_t)b * NG + g) * D + d];
    g_gsum[g * D + d] = s;
    if (d == 0) {
        int c = 0;
        for (int b = 0; b < 64; b++) c += g_gcntp[b * NG + g];
        g_gcnt[g] = (float)c;
    }
}

// ---------------- 8: graph heads ----------------
__global__ void graph_head_kernel(const float* __restrict__ gc_w1, const float* __restrict__ gc_b1,
                                  const float* __restrict__ gc_w2, const float* __restrict__ gc_b2,
                                  const float* __restrict__ rs_w1, const float* __restrict__ rs_b1,
                                  const float* __restrict__ rs_w2, const float* __restrict__ rs_b2,
                                  float* __restrict__ graph_logits, float* __restrict__ risk) {
    __shared__ float ge[D];
    __shared__ float hid[64];
    __shared__ float hid2[32];
    int d = threadIdx.x;  // 256
    for (int g = 0; g < NG; g++) {
        float cnt = fmaxf(g_gcnt[g], 1.0f);
        ge[d] = g_gsum[g * D + d] / cnt;
        __syncthreads();
        if (d < 64) {
            float s = gc_b1[d];
            for (int k = 0; k < D; k++) s += ge[k] * gc_w1[k * 64 + d];
            hid[d] = gelu_exact(s);
        } else if (d < 96) {
            int t = d - 64;
            float s = rs_b1[t];
            for (int k = 0; k < D; k++) s += ge[k] * rs_w1[k * 32 + t];
            hid2[t] = gelu_exact(s);
        }
        __syncthreads();
        if (d < 3) {
            float s = gc_b2[d];
            for (int k = 0; k < 64; k++) s += hid[k] * gc_w2[k * 3 + d];
            graph_logits[g * 3 + d] = s;
        }
        if (d == 3) {
            float s = rs_b2[0];
            for (int k = 0; k < 32; k++) s += hid2[k] * rs_w2[k];
            risk[g] = 1.0f / (1.0f + expf(-s));
        }
        __syncthreads();
    }
}

// ---------------- launch ----------------
extern "C" void kernel_launch(void* const* d_in, const int* in_sizes, int n_in,
                              void* d_out, int out_size) {
    const float* x    = (const float*)d_in[0];
    const float* adj  = (const float*)d_in[1];
    const int*   mask = (const int*)d_in[2];
    const float* W[3]   = {(const float*)d_in[3], (const float*)d_in[5], (const float*)d_in[7]};
    const float* a[3]   = {(const float*)d_in[4], (const float*)d_in[6], (const float*)d_in[8]};
    const float* lng[3] = {(const float*)d_in[9],  (const float*)d_in[11], (const float*)d_in[13]};
    const float* lnb[3] = {(const float*)d_in[10], (const float*)d_in[12], (const float*)d_in[14]};
    const float* nc_w1 = (const float*)d_in[15];
    const float* nc_b1 = (const float*)d_in[16];
    const float* nc_w2 = (const float*)d_in[17];
    const float* nc_b2 = (const float*)d_in[18];
    const float* gc_w1 = (const float*)d_in[19];
    const float* gc_b1 = (const float*)d_in[20];
    const float* gc_w2 = (const float*)d_in[21];
    const float* gc_b2 = (const float*)d_in[22];
    const float* rs_w1 = (const float*)d_in[23];
    const float* rs_b1 = (const float*)d_in[24];
    const float* rs_w2 = (const float*)d_in[25];
    const float* rs_b2 = (const float*)d_in[26];

    float* out = (float*)d_out;
    float* out_node  = out;                 // 8192*5
    float* out_graph = out + 40960;         // 8*3
    float* out_risk  = out + 40984;         // 8
    float* out_h3    = out + 40992;         // 8192*256

    // resolve device-global scratch addresses
    float *pX1, *pX2;
    cudaGetSymbolAddress((void**)&pX1, g_X1);
    cudaGetSymbolAddress((void**)&pX2, g_X2);
    void *pXh, *pWh;
    cudaGetSymbolAddress(&pXh, g_Xh);
    cudaGetSymbolAddress(&pWh, g_Wh);
    float* pmid; cudaGetSymbolAddress((void**)&pmid, g_mid);

    cudaFuncSetAttribute(gat_tile3_kernel, cudaFuncAttributeMaxDynamicSharedMemorySize,
                         GT3_SMEM_BYTES);

    build_ell_kernel<<<N_NODES, 256>>>(adj);
    cvt_half_kernel<<<2048, 256>>>(x, (__half2*)pXh);   // layer-1 fp16 input

    const float* Xprev = x;
    float* Xouts[3] = {pX1, pX2, out_h3};
    for (int L = 0; L < 3; L++) {
        wavec_kernel<<<1, 256>>>(W[L], a[L]);
        s12_kernel<<<N_NODES / 8, 256>>>(Xprev);
        cvt_half_kernel<<<64, 256>>>(W[L], (__half2*)pWh);
        h16_gemm_kernel<<<dim3(4, 64), 256>>>((const __half*)pXh, (const __half*)pWh);
        colsum_part_kernel<<<32, 256>>>();
        colsum_red_kernel<<<1, 256>>>();
        coef_kernel<<<N_NODES / 8, 256>>>();
        // writes fp32 output AND its fp16 copy (input of next layer's h16_gemm)
        gat_tile3_kernel<<<128, 512, GT3_SMEM_BYTES>>>(Xprev, lng[L], lnb[L], Xouts[L],
                                                       (__half2*)pXh, L > 0 ? 1 : 0);
        Xprev = Xouts[L];
    }

    // node head: mid = gelu(h3 @ nc_w1 + b1); logits = mid @ nc_w2 + b2
    gemm_kernel<1, 0><<<dim3(1, N_NODES / 128), 256>>>(out_h3, nc_w1, nc_b1, pmid,
                                                       N_NODES, 64, D);
    node_logits_kernel<<<N_NODES, 64>>>(pmid, nc_w2, nc_b2, out_node);

    // graph heads
    pool_part_kernel<<<64, 256>>>(out_h3, mask);
    pool_red_kernel<<<NG, 256>>>();
    graph_head_kernel<<<1, 256>>>(gc_w1, gc_b1, gc_w2, gc_b2,
                                  rs_w1, rs_b1, rs_w2, rs_b2,
                                  out_graph, out_risk);
}

// round 17
// speedup vs baseline: 1.7925x; 1.7925x over previous
#include <cuda_runtime.h>
#include <cuda_fp16.h>
#include <math.h>
#include <stdint.h>

#define N_NODES 8192
#define D 256
#define NG 8
#define ELLW 768   // max row degree bound; binomial(8192,0.05) max ~ 490

// ---------------- device scratch (no allocations allowed) ----------------
__device__ unsigned short g_cols[(size_t)N_NODES * ELLW];
__device__ int            g_deg[N_NODES];
__device__ float          g_X1[(size_t)N_NODES * D];
__device__ float          g_X2[(size_t)N_NODES * D];
__device__ __half2        g_Xh[(size_t)N_NODES * (D / 2)];   // fp16 copy of layer input / h3
__device__ __half2        g_Wh[(size_t)D * (D / 2)];         // fp16 copy of W (or nc_w1)
__device__ __half2        g_h2[(size_t)N_NODES * (D / 2)];   // h = X @ W, fp16 row-major
__device__ float          g_s1[N_NODES];
__device__ float          g_s2[N_NODES];
__device__ float          g_wa[D];
__device__ float          g_wb[D];
__device__ float          g_Spart[32][D];
__device__ float          g_S[D];
__device__ float          g_mid[(size_t)N_NODES * 64];
__device__ float          g_gpart[(size_t)64 * NG * D];
__device__ int            g_gcntp[64 * NG];
__device__ float          g_gsum[NG * D];
__device__ float          g_gcnt[NG];

// ---------------- helpers ----------------
__device__ __forceinline__ float gelu_exact(float x) {
    return 0.5f * x * (1.0f + erff(x * 0.70710678118654752f));
}

__device__ __forceinline__ uint32_t smem_addr(const void* p) {
    return (uint32_t)__cvta_generic_to_shared(p);
}

__device__ __forceinline__ void ldsm_x4(uint32_t addr, uint32_t& r0, uint32_t& r1,
                                        uint32_t& r2, uint32_t& r3) {
    asm volatile("ldmatrix.sync.aligned.m8n8.x4.shared.b16 {%0,%1,%2,%3}, [%4];"
                 : "=r"(r0), "=r"(r1), "=r"(r2), "=r"(r3) : "r"(addr));
}

__device__ __forceinline__ void ldsm_x2_trans(uint32_t addr, uint32_t& r0, uint32_t& r1) {
    asm volatile("ldmatrix.sync.aligned.m8n8.x2.trans.shared.b16 {%0,%1}, [%2];"
                 : "=r"(r0), "=r"(r1) : "r"(addr));
}

__device__ __forceinline__ void mma16816(float* c, uint32_t a0, uint32_t a1, uint32_t a2,
                                         uint32_t a3, uint32_t b0, uint32_t b1) {
    asm volatile(
        "mma.sync.aligned.m16n8k16.row.col.f32.f16.f16.f32 "
        "{%0,%1,%2,%3}, {%4,%5,%6,%7}, {%8,%9}, {%0,%1,%2,%3};"
        : "+f"(c[0]), "+f"(c[1]), "+f"(c[2]), "+f"(c[3])
        : "r"(a0), "r"(a1), "r"(a2), "r"(a3), "r"(b0), "r"(b1));
}

__device__ __forceinline__ float block_sum_256(float v, volatile float* red) {
    int lane = threadIdx.x & 31, w = threadIdx.x >> 5;
#pragma unroll
    for (int o = 16; o > 0; o >>= 1) v += __shfl_down_sync(0xffffffffu, v, o);
    __syncthreads();
    if (lane == 0) red[w] = v;
    __syncthreads();
    float s = 0.0f;
#pragma unroll
    for (int k = 0; k < 8; k++) s += red[k];
    return s;
}

__device__ __forceinline__ float block_max_256(float v, volatile float* red) {
    int lane = threadIdx.x & 31, w = threadIdx.x >> 5;
#pragma unroll
    for (int o = 16; o > 0; o >>= 1) v = fmaxf(v, __shfl_down_sync(0xffffffffu, v, o));
    __syncthreads();
    if (lane == 0) red[w] = v;
    __syncthreads();
    float s = -1e30f;
#pragma unroll
    for (int k = 0; k < 8; k++) s = fmaxf(s, red[k]);
    return s;
}

// ---------------- 0: dense adj -> ELL (deterministic, sorted cols) ----------------
__global__ void build_ell_kernel(const float* __restrict__ adj) {
    int i = blockIdx.x;
    int tid = threadIdx.x;             // 256
    int lane = tid & 31, w = tid >> 5;
    __shared__ int wcnt[8];
    const float* row = adj + (size_t)i * N_NODES;
    int base = 0;
    for (int c0 = 0; c0 < N_NODES; c0 += 256) {
        int c = c0 + tid;
        bool pred = (row[c] != 0.0f);
        unsigned bal = __ballot_sync(0xffffffffu, pred);
        if (lane == 0) wcnt[w] = __popc(bal);
        __syncthreads();
        int off = 0, tot = 0;
#pragma unroll
        for (int k = 0; k < 8; k++) { int v = wcnt[k]; tot += v; if (k < w) off += v; }
        if (pred) {
            int pos = base + off + __popc(bal & ((1u << lane) - 1u));
            if (pos < ELLW) g_cols[(size_t)i * ELLW + pos] = (unsigned short)c;
        }
        base += tot;
        __syncthreads();
    }
    if (tid == 0) g_deg[i] = (base < ELLW) ? base : ELLW;
}

// ---------------- 1: wa = W @ a_top, wb = W @ a_bot ----------------
__global__ void wavec_kernel(const float* __restrict__ W, const float* __restrict__ a) {
    __shared__ float at[D], ab[D];
    int t = threadIdx.x; // 256
    at[t] = a[t];
    ab[t] = a[D + t];
    __syncthreads();
    float s1 = 0.0f, s2 = 0.0f;
    const float* wr = W + (size_t)t * D;
#pragma unroll 8
    for (int c = 0; c < D; c++) { float w = wr[c]; s1 += w * at[c]; s2 += w * ab[c]; }
    g_wa[t] = s1;
    g_wb[t] = s2;
}

// ---------------- 2: s1 = X @ wa, s2 = X @ wb (fp32 exact logit path) ----------------
__global__ void s12_kernel(const float* __restrict__ X) {
    int w = threadIdx.x >> 5, lane = threadIdx.x & 31;
    int i = blockIdx.x * 8 + w;
    const float* xr = X + (size_t)i * D;
    float a1 = 0.0f, a2 = 0.0f;
#pragma unroll
    for (int jj = 0; jj < 8; jj++) {
        int j = jj * 32 + lane;
        float x = xr[j];
        a1 += x * g_wa[j];
        a2 += x * g_wb[j];
    }
#pragma unroll
    for (int o = 16; o > 0; o >>= 1) {
        a1 += __shfl_down_sync(0xffffffffu, a1, o);
        a2 += __shfl_down_sync(0xffffffffu, a2, o);
    }
    if (lane == 0) { g_s1[i] = a1; g_s2[i] = a2; }
}

// ---------------- 2b: fp32 -> fp16 conversion (4 floats per thread) ----------------
__global__ void cvt_half_kernel(const float* __restrict__ A, __half2* __restrict__ O) {
    int idx = blockIdx.x * blockDim.x + threadIdx.x;
    float4 v = reinterpret_cast<const float4*>(A)[idx];
    O[idx * 2]     = __floats2half2_rn(v.x, v.y);
    O[idx * 2 + 1] = __floats2half2_rn(v.z, v.w);
}

// ---------------- 3: fp16 tensor GEMM  C = A(Mx256) @ B(256xN), N=64 per block col ----
// EPI 0: write fp16 to g_h2 (stride 256). EPI 1: bias+gelu -> fp32 outF (width 64).
// Fragment math identical to the validated R10 h16_gemm.
template <int EPI>
__global__ __launch_bounds__(256) void h16_gemm_kernel(const __half* __restrict__ Ah,
                                                       const __half* __restrict__ Bh,
                                                       int ldb,
                                                       const float* __restrict__ bias,
                                                       float* __restrict__ outF) {
    __shared__ __align__(16) __half As[128 * 72];   // row stride 144 B (conflict-free ldsm)
    __shared__ __align__(16) __half Bs[64 * 72];
    const int tid = threadIdx.x, lane = tid & 31, wid = tid >> 5;
    const int wm = wid >> 1, wn = wid & 1;
    const int m0 = blockIdx.y * 128, n0 = blockIdx.x * 64;
    float acc[2][4][4];
#pragma unroll
    for (int m = 0; m < 2; m++)
#pragma unroll
        for (int n = 0; n < 4; n++)
#pragma unroll
            for (int j = 0; j < 4; j++) acc[m][n][j] = 0.0f;

    const uint32_t as_base = smem_addr(As);
    const uint32_t bs_base = smem_addr(Bs);
    const int ar = tid >> 1, aq = (tid & 1) * 4;
    const int br = tid >> 2, bq = (tid & 3) * 2;

    for (int kt = 0; kt < 4; kt++) {
        int k0 = kt * 64;
        {
            const uint4* asrc = reinterpret_cast<const uint4*>(Ah + (size_t)(m0 + ar) * 256 + k0);
            uint4* adst = reinterpret_cast<uint4*>(As + ar * 72);
#pragma unroll
            for (int c = 0; c < 4; c++) adst[aq + c] = asrc[aq + c];
        }
        {
            const uint4* bsrc = reinterpret_cast<const uint4*>(Bh + (size_t)(k0 + br) * ldb + n0);
            uint4* bdst = reinterpret_cast<uint4*>(Bs + br * 72);
            bdst[bq] = bsrc[bq];
            bdst[bq + 1] = bsrc[bq + 1];
        }
        __syncthreads();
#pragma unroll
        for (int k8 = 0; k8 < 4; k8++) {
            uint32_t a0[2], a1[2], a2[2], a3[2];
#pragma unroll
            for (int m = 0; m < 2; m++) {
                uint32_t addr = as_base +
                    (uint32_t)((wm * 32 + m * 16 + (lane & 15)) * 144 + (lane >> 4) * 16 + k8 * 32);
                ldsm_x4(addr, a0[m], a1[m], a2[m], a3[m]);
            }
#pragma unroll
            for (int n8 = 0; n8 < 4; n8++) {
                uint32_t baddr = bs_base +
                    (uint32_t)((k8 * 16 + (lane & 15)) * 144 + (wn * 32 + n8 * 8) * 2);
                uint32_t b0, b1;
                ldsm_x2_trans(baddr, b0, b1);
                mma16816(acc[0][n8], a0[0], a1[0], a2[0], a3[0], b0, b1);
                mma16816(acc[1][n8], a0[1], a1[1], a2[1], a3[1], b0, b1);
            }
        }
        __syncthreads();
    }
#pragma unroll
    for (int m = 0; m < 2; m++) {
        int r = m0 + wm * 32 + m * 16 + (lane >> 2);
#pragma unroll
        for (int n8 = 0; n8 < 4; n8++) {
            int cidx = n0 + wn * 32 + n8 * 8 + (lane & 3) * 2;
            if (EPI == 0) {
                g_h2[(size_t)r * 128 + (cidx >> 1)] =
                    __floats2half2_rn(acc[m][n8][0], acc[m][n8][1]);
                g_h2[(size_t)(r + 8) * 128 + (cidx >> 1)] =
                    __floats2half2_rn(acc[m][n8][2], acc[m][n8][3]);
            } else {
                float b0v = bias[cidx], b1v = bias[cidx + 1];
                outF[(size_t)r * 64 + cidx]       = gelu_exact(acc[m][n8][0] + b0v);
                outF[(size_t)r * 64 + cidx + 1]   = gelu_exact(acc[m][n8][1] + b1v);
                outF[(size_t)(r + 8) * 64 + cidx]     = gelu_exact(acc[m][n8][2] + b0v);
                outF[(size_t)(r + 8) * 64 + cidx + 1] = gelu_exact(acc[m][n8][3] + b1v);
            }
        }
    }
}

// ---------------- 4: column sum of h ----------------
__global__ void colsum_part_kernel() {
    int d = threadIdx.x, b = blockIdx.x;  // 32 blocks
    const __half* h = reinterpret_cast<const __half*>(g_h2);
    float s = 0.0f;
    int r0 = b * (N_NODES / 32);
    for (int r = r0; r < r0 + (N_NODES / 32); r++) s += __half2float(h[(size_t)r * D + d]);
    g_Spart[b][d] = s;
}
__global__ void colsum_red_kernel() {
    int d = threadIdx.x;
    float s = 0.0f;
#pragma unroll
    for (int b = 0; b < 32; b++) s += g_Spart[b][d];
    g_S[d] = s;
}

// ---------------- 5: GAT row (256 thr, warp-wide row loads) + ELU + LN + residual ----------------
__global__ __launch_bounds__(256) void gat_row2_kernel(const float* __restrict__ Xin,
                                                       const float* __restrict__ lng,
                                                       const float* __restrict__ lnb,
                                                       float* __restrict__ Xout,
                                                       __half* __restrict__ XoutH,
                                                       int residual) {
    const int i = blockIdx.x;
    const int t = threadIdx.x, lane = t & 31, w = t >> 5;   // 8 warps
    __shared__ int   cols_sm[ELLW];
    __shared__ float coef_sm[ELLW];
    __shared__ float wpart[8][288];   // stride-9 per lane: idx = lane*9 + f (conflict-free)
    __shared__ float red[8];

    const int deg = g_deg[i];
    const float s1 = g_s1[i];
    const unsigned short* __restrict__ crow = g_cols + (size_t)i * ELLW;

    for (int k = t; k < deg; k += 256) {
        int j = (int)crow[k];
        cols_sm[k] = j;
        coef_sm[k] = g_s2[j];
    }
    __syncthreads();

    // exact row max: m = max(0, lrelu(s1 + max_j s2_j))   (deg==0 -> huge-neg -> m=0)
    float tmax = -1e30f;
    for (int k = t; k < deg; k += 256) tmax = fmaxf(tmax, coef_sm[k]);
    tmax = block_max_256(tmax, red);
    float z0 = s1 + tmax;
    float lr0 = (z0 > 0.0f) ? z0 : 0.2f * z0;
    const float m = fmaxf(lr0, 0.0f);
    const float q = __expf(-m);   // exp(e-m) at every non-edge (e=0)

    float zp = 0.0f;
    for (int k = t; k < deg; k += 256) {
        float z = s1 + coef_sm[k];
        float lr = (z > 0.0f) ? z : 0.2f * z;
        float p = __expf(lr - m);
        zp += p;
        coef_sm[k] = p - q;
    }
    const float Z = block_sum_256(zp, red) + (float)(N_NODES - deg) * q;  // syncs publish coef_sm

    // SpMM: warp w takes edges k = w, w+8, ...; lane owns features [8*lane, 8*lane+8)
    float acc[8];
#pragma unroll
    for (int f = 0; f < 8; f++) acc[f] = 0.0f;
    const uint4* __restrict__ hsrc = reinterpret_cast<const uint4*>(g_h2);
#pragma unroll 4
    for (int k = w; k < deg; k += 8) {
        float c = coef_sm[k];             // broadcast LDS
        int j = cols_sm[k];               // broadcast LDS
        uint4 v = __ldg(&hsrc[((size_t)j << 5) + lane]);   // whole row per warp, LDG.128
        const __half2* hv = reinterpret_cast<const __half2*>(&v);
        float2 f0 = __half22float2(hv[0]);
        float2 f1 = __half22float2(hv[1]);
        float2 f2 = __half22float2(hv[2]);
        float2 f3 = __half22float2(hv[3]);
        acc[0] += c * f0.x; acc[1] += c * f0.y;
        acc[2] += c * f1.x; acc[3] += c * f1.y;
        acc[4] += c * f2.x; acc[5] += c * f2.y;
        acc[6] += c * f3.x; acc[7] += c * f3.y;
    }
#pragma unroll
    for (int f = 0; f < 8; f++) wpart[w][lane * 9 + f] = acc[f];   // conflict-free (9l+f mod 32)
    __syncthreads();

    // thread t owns feature t
    float v;
    {
        int idx = (t >> 3) * 9 + (t & 7);
        float s = 0.0f;
#pragma unroll
        for (int ww = 0; ww < 8; ww++) s += wpart[ww][idx];
        v = (s + q * g_S[t]) / Z;
        v = (v > 0.0f) ? v : expm1f(v);
    }

    // LayerNorm over 256 features (biased var, eps 1e-5) + residual
    float sum = block_sum_256(v, red);
    float mean = sum * (1.0f / 256.0f);
    float d = v - mean;
    float sq = block_sum_256(d * d, red);
    float rstd = rsqrtf(sq * (1.0f / 256.0f) + 1e-5f);
    float y = d * rstd * lng[t] + lnb[t];
    if (residual) y += Xin[(size_t)i * D + t];
    Xout[(size_t)i * D + t] = y;
    XoutH[(size_t)i * D + t] = __float2half(y);   // fp16 copy (next layer / head input)
}

// ---------------- 6: node logits (8192x64)@(64x5)+b ----------------
__global__ void node_logits_kernel(const float* __restrict__ mid, const float* __restrict__ w2,
                                   const float* __restrict__ b2, float* __restrict__ out) {
    int i = blockIdx.x, t = threadIdx.x;  // 64
    __shared__ float sm[64];
    sm[t] = mid[(size_t)i * 64 + t];
    __syncthreads();
    if (t < 5) {
        float s = b2[t];
#pragma unroll 8
        for (int k = 0; k < 64; k++) s += sm[k] * w2[k * 5 + t];
        out[(size_t)i * 5 + t] = s;
    }
}

// ---------------- 7: deterministic segment pooling ----------------
__global__ void pool_part_kernel(const float* __restrict__ h3, const int* __restrict__ mask) {
    __shared__ float sacc[NG * D];
    int d = threadIdx.x;  // 256
    int b = blockIdx.x;   // 64 blocks x 128 rows
#pragma unroll
    for (int g = 0; g < NG; g++) sacc[g * D + d] = 0.0f;
    __syncthreads();
    int r0 = b * 128, lc = 0;
    for (int r = r0; r < r0 + 128; r++) {
        int g = mask[r];
        sacc[g * D + d] += h3[(size_t)r * D + d];
        if (d < NG && g == d) lc++;
    }
    __syncthreads();
#pragma unroll
    for (int g = 0; g < NG; g++)
        g_gpart[((size_t)b * NG + g) * D + d] = sacc[g * D + d];
    if (d < NG) g_gcntp[b * NG + d] = lc;
}
__global__ void pool_red_kernel() {
    int g = blockIdx.x, d = threadIdx.x;  // 8 x 256
    float s = 0.0f;
    for (int b = 0; b < 64; b++) s += g_gpart[((size_t)b * NG + g) * D + d];
    g_gsum[g * D + d] = s;
    if (d == 0) {
        int c = 0;
        for (int b = 0; b < 64; b++) c += g_gcntp[b * NG + g];
        g_gcnt[g] = (float)c;
    }
}

// ---------------- 8: graph heads ----------------
__global__ void graph_head_kernel(const float* __restrict__ gc_w1, const float* __restrict__ gc_b1,
                                  const float* __restrict__ gc_w2, const float* __restrict__ gc_b2,
                                  const float* __restrict__ rs_w1, const float* __restrict__ rs_b1,
                                  const float* __restrict__ rs_w2, const float* __restrict__ rs_b2,
                                  float* __restrict__ graph_logits, float* __restrict__ risk) {
    __shared__ float ge[D];
    __shared__ float hid[64];
    __shared__ float hid2[32];
    int d = threadIdx.x;  // 256
    for (int g = 0; g < NG; g++) {
        float cnt = fmaxf(g_gcnt[g], 1.0f);
        ge[d] = g_gsum[g * D + d] / cnt;
        __syncthreads();
        if (d < 64) {
            float s = gc_b1[d];
            for (int k = 0; k < D; k++) s += ge[k] * gc_w1[k * 64 + d];
            hid[d] = gelu_exact(s);
        } else if (d < 96) {
            int t = d - 64;
            float s = rs_b1[t];
            for (int k = 0; k < D; k++) s += ge[k] * rs_w1[k * 32 + t];
            hid2[t] = gelu_exact(s);
        }
        __syncthreads();
        if (d < 3) {
            float s = gc_b2[d];
            for (int k = 0; k < 64; k++) s += hid[k] * gc_w2[k * 3 + d];
            graph_logits[g * 3 + d] = s;
        }
        if (d == 3) {
            float s = rs_b2[0];
            for (int k = 0; k < 32; k++) s += hid2[k] * rs_w2[k];
            risk[g] = 1.0f / (1.0f + expf(-s));
        }
        __syncthreads();
    }
}

// ---------------- launch ----------------
extern "C" void kernel_launch(void* const* d_in, const int* in_sizes, int n_in,
                              void* d_out, int out_size) {
    const float* x    = (const float*)d_in[0];
    const float* adj  = (const float*)d_in[1];
    const int*   mask = (const int*)d_in[2];
    const float* W[3]   = {(const float*)d_in[3], (const float*)d_in[5], (const float*)d_in[7]};
    const float* a[3]   = {(const float*)d_in[4], (const float*)d_in[6], (const float*)d_in[8]};
    const float* lng[3] = {(const float*)d_in[9],  (const float*)d_in[11], (const float*)d_in[13]};
    const float* lnb[3] = {(const float*)d_in[10], (const float*)d_in[12], (const float*)d_in[14]};
    const float* nc_w1 = (const float*)d_in[15];
    const float* nc_b1 = (const float*)d_in[16];
    const float* nc_w2 = (const float*)d_in[17];
    const float* nc_b2 = (const float*)d_in[18];
    const float* gc_w1 = (const float*)d_in[19];
    const float* gc_b1 = (const float*)d_in[20];
    const float* gc_w2 = (const float*)d_in[21];
    const float* gc_b2 = (const float*)d_in[22];
    const float* rs_w1 = (const float*)d_in[23];
    const float* rs_b1 = (const float*)d_in[24];
    const float* rs_w2 = (const float*)d_in[25];
    const float* rs_b2 = (const float*)d_in[26];

    float* out = (float*)d_out;
    float* out_node  = out;                 // 8192*5
    float* out_graph = out + 40960;         // 8*3
    float* out_risk  = out + 40984;         // 8
    float* out_h3    = out + 40992;         // 8192*256

    // resolve device-global scratch addresses
    float *pX1, *pX2;
    cudaGetSymbolAddress((void**)&pX1, g_X1);
    cudaGetSymbolAddress((void**)&pX2, g_X2);
    void *pXh, *pWh;
    cudaGetSymbolAddress(&pXh, g_Xh);
    cudaGetSymbolAddress(&pWh, g_Wh);
    float* pmid; cudaGetSymbolAddress((void**)&pmid, g_mid);

    build_ell_kernel<<<N_NODES, 256>>>(adj);
    cvt_half_kernel<<<2048, 256>>>(x, (__half2*)pXh);   // layer-1 fp16 input

    const float* Xprev = x;
    float* Xouts[3] = {pX1, pX2, out_h3};
    for (int L = 0; L < 3; L++) {
        wavec_kernel<<<1, 256>>>(W[L], a[L]);
        s12_kernel<<<N_NODES / 8, 256>>>(Xprev);
        cvt_half_kernel<<<64, 256>>>(W[L], (__half2*)pWh);
        h16_gemm_kernel<0><<<dim3(4, 64), 256>>>((const __half*)pXh, (const __half*)pWh,
                                                 256, nullptr, nullptr);
        colsum_part_kernel<<<32, 256>>>();
        colsum_red_kernel<<<1, 256>>>();
        // writes fp32 output AND fp16 copy into g_Xh (next layer / node-head input)
        gat_row2_kernel<<<N_NODES, 256>>>(Xprev, lng[L], lnb[L], Xouts[L],
                                          (__half*)pXh, L > 0 ? 1 : 0);
        Xprev = Xouts[L];
    }

    // node head: mid = gelu(h3 @ nc_w1 + b1) via fp16 tensor GEMM; logits fp32
    cvt_half_kernel<<<16, 256>>>(nc_w1, (__half2*)pWh);   // 256x64 weights
    h16_gemm_kernel<1><<<dim3(1, 64), 256>>>((const __half*)pXh, (const __half*)pWh,
                                             64, nc_b1, pmid);
    node_logits_kernel<<<N_NODES, 64>>>(pmid, nc_w2, nc_b2, out_node);

    // graph heads
    pool_part_kernel<<<64, 256>>>(out_h3, mask);
    pool_red_kernel<<<NG, 256>>>();
    graph_head_kernel<<<1, 256>>>(gc_w1, gc_b1, gc_w2, gc_b2,
                                  rs_w1, rs_b1, rs_w2, rs_b2,
                                  out_graph, out_risk);
}